// round 9
// baseline (speedup 1.0000x reference)
#include <cuda_runtime.h>
#include <cuda_fp16.h>

#define NMAX 10000
#define H1 4
#define C 128
#define F1 512
#define ELLW 256   // max indegree capacity (Poisson(32) graph: max ~60)

// ---------------- scratch (static __device__) ----------------
__device__ int      g_is64;
__device__ int      g_cur[NMAX];
__device__ int      g_ell[NMAX * ELLW];
__device__ float    g_c[16];             // cs0[4], cs1[4], cd0[4], cd1[4]
__device__ unsigned g_smax1[H1];         // ord-transformed global max of s per head
__device__ unsigned g_as2max1;           // ord-transformed global max of as2
__device__ __align__(16) float g_a0[NMAX * 4];
__device__ __align__(16) float g_a1[NMAX * 4];
__device__ __align__(16) __half2 g_h2h[NMAX * (C / 2)];
__device__ float g_as2[NMAX];
__device__ float g_ad2[NMAX];

__device__ __forceinline__ float lrelu(float v) { return v > 0.f ? v : 0.2f * v; }

// monotone float<->unsigned order transform (for atomicMax on floats)
__device__ __forceinline__ unsigned f2ord(float f) {
    unsigned b = __float_as_uint(f);
    return b ^ ((unsigned)((int)b >> 31) | 0x80000000u);
}
__device__ __forceinline__ float ord2f(unsigned u) {
    unsigned b = (u & 0x80000000u) ? (u ^ 0x80000000u) : ~u;
    return __uint_as_float(b);
}

// ---- packed f32x2 helpers ----
__device__ __forceinline__ unsigned long long pack_f2(float lo, float hi) {
    unsigned long long r;
    asm("mov.b64 %0, {%1, %2};" : "=l"(r) : "f"(lo), "f"(hi));
    return r;
}
__device__ __forceinline__ void fma_f32x2(unsigned long long& d,
                                          unsigned long long a, unsigned long long b) {
    asm("fma.rn.f32x2 %0, %1, %2, %3;" : "=l"(d) : "l"(a), "l"(b), "l"(d));
}
__device__ __forceinline__ float2 unpack_f2(unsigned long long v) {
    float lo, hi;
    asm("mov.b64 {%0, %1}, %2;" : "=f"(lo), "=f"(hi) : "l"(v));
    return make_float2(lo, hi);
}

// ---------------- prep: rank-2 constants + dtype detect + max resets ----------------
__global__ void prep_kernel(const int* __restrict__ ei32, const float* __restrict__ W1,
                            const float* __restrict__ asw, const float* __restrict__ adw) {
    int t = threadIdx.x;                 // 128
    int h = t >> 5, lane = t & 31;
    float cs0 = 0.f, cs1 = 0.f, cd0 = 0.f, cd1 = 0.f;
#pragma unroll
    for (int i = 0; i < 4; i++) {
        int f = h * C + lane + 32 * i;
        float w0 = W1[f], w1 = W1[F1 + f];
        float as = asw[f], ad = adw[f];
        cs0 += w0 * as; cs1 += w1 * as;
        cd0 += w0 * ad; cd1 += w1 * ad;
    }
#pragma unroll
    for (int o = 16; o > 0; o >>= 1) {
        cs0 += __shfl_down_sync(0xFFFFFFFFu, cs0, o);
        cs1 += __shfl_down_sync(0xFFFFFFFFu, cs1, o);
        cd0 += __shfl_down_sync(0xFFFFFFFFu, cd0, o);
        cd1 += __shfl_down_sync(0xFFFFFFFFu, cd1, o);
    }
    if (lane == 0) {
        g_c[h] = cs0; g_c[4 + h] = cs1; g_c[8 + h] = cd0; g_c[12 + h] = cd1;
    }
    if (t < H1) g_smax1[t] = 0u;
    if (t == 4) g_as2max1 = 0u;
    if (t == 5) {
        int allzero = 1;
        for (int k = 1; k < 128; k += 2)
            if (ei32[k] != 0) { allzero = 0; break; }
        g_is64 = allzero;
    }
}

// ---------------- ELL init + global s-max per head ----------------
__global__ void ell_init_kernel(const float* __restrict__ x, int n) {
    int i = blockIdx.x * blockDim.x + threadIdx.x;
    int lane = threadIdx.x & 31;
    float s[H1];
#pragma unroll
    for (int h = 0; h < H1; h++) s[h] = -1e30f;
    if (i < n) {
        g_cur[i] = 1;
        g_ell[i * ELLW] = i;
        float2 xv = *reinterpret_cast<const float2*>(x + 2 * i);
#pragma unroll
        for (int h = 0; h < H1; h++)
            s[h] = xv.x * g_c[h] + xv.y * g_c[4 + h];
    }
#pragma unroll
    for (int o = 16; o > 0; o >>= 1)
#pragma unroll
        for (int h = 0; h < H1; h++)
            s[h] = fmaxf(s[h], __shfl_xor_sync(0xFFFFFFFFu, s[h], o));
    if (lane == 0) {
#pragma unroll
        for (int h = 0; h < H1; h++)
            atomicMax(&g_smax1[h], f2ord(s[h]));
    }
}

__global__ void scatter_kernel(const int* __restrict__ ei32, int e) {
    int i = blockIdx.x * blockDim.x + threadIdx.x;
    if (i >= e) return;
    int src, dst;
    if (g_is64) {
        const long long* e64 = (const long long*)ei32;
        src = (int)e64[i];
        dst = (int)e64[e + i];
    } else {
        src = ei32[i];
        dst = ei32[e + i];
    }
    int pos = atomicAdd(&g_cur[dst], 1);
    if (pos < ELLW) g_ell[dst * ELLW + pos] = src;
}

// ---------------- layer 1: warp-per-node rank-2 GAT, SINGLE PASS ----------------
__global__ void __launch_bounds__(256) gat1_kernel(const float* __restrict__ x, int n) {
    __shared__ float cs[16];
    __shared__ float smax[H1];
    int tid = threadIdx.x;
    if (tid < 16) cs[tid] = g_c[tid];
    if (tid >= 16 && tid < 16 + H1) smax[tid - 16] = ord2f(g_smax1[tid - 16]);
    __syncthreads();
    int w = tid >> 5, lane = tid & 31;
    int node = blockIdx.x * 8 + w;
    if (node >= n) return;

    int deg = min(g_cur[node], ELLW);
    const int* row = g_ell + node * ELLW;

    float xd0 = x[2 * node], xd1 = x[2 * node + 1];
    float bound[H1];
#pragma unroll
    for (int h = 0; h < H1; h++) {
        float dh = xd0 * cs[8 + h] + xd1 * cs[12 + h];
        bound[h] = lrelu(smax[h] + dh);
        // fold dh into per-head shifted constants: e = lrelu(s + dh); keep dh separately
    }
    float dh[H1];
#pragma unroll
    for (int h = 0; h < H1; h++) dh[h] = xd0 * cs[8 + h] + xd1 * cs[12 + h];

    float sp[H1] = {0.f, 0.f, 0.f, 0.f};
    float s0[H1] = {0.f, 0.f, 0.f, 0.f};
    float s1[H1] = {0.f, 0.f, 0.f, 0.f};
    for (int j = lane; j < deg; j += 32) {
        int src = row[j];
        float2 xs = *reinterpret_cast<const float2*>(x + 2 * src);
#pragma unroll
        for (int h = 0; h < H1; h++) {
            float e = lrelu(xs.x * cs[h] + xs.y * cs[4 + h] + dh[h]);
            float p = __expf(e - bound[h]);
            sp[h] += p;
            s0[h] += p * xs.x;
            s1[h] += p * xs.y;
        }
    }
#pragma unroll
    for (int o = 16; o > 0; o >>= 1)
#pragma unroll
        for (int h = 0; h < H1; h++) {
            sp[h] += __shfl_down_sync(0xFFFFFFFFu, sp[h], o);
            s0[h] += __shfl_down_sync(0xFFFFFFFFu, s0[h], o);
            s1[h] += __shfl_down_sync(0xFFFFFFFFu, s1[h], o);
        }
    if (lane == 0) {
        float4 a0, a1;
        float i0 = 1.f / (sp[0] + 1e-16f);
        float i1 = 1.f / (sp[1] + 1e-16f);
        float i2 = 1.f / (sp[2] + 1e-16f);
        float i3 = 1.f / (sp[3] + 1e-16f);
        a0.x = s0[0] * i0; a0.y = s0[1] * i1; a0.z = s0[2] * i2; a0.w = s0[3] * i3;
        a1.x = s1[0] * i0; a1.y = s1[1] * i1; a1.z = s1[2] * i2; a1.w = s1[3] * i3;
        ((float4*)g_a0)[node] = a0;
        ((float4*)g_a1)[node] = a1;
    }
}

// ---------------- layer 2 GEMM + fused out1 reconstruction + attn2 dots + as2 max ----------------
__global__ void __launch_bounds__(256) gemm2_kernel(const float* __restrict__ W2,
                             const float* __restrict__ asw, const float* __restrict__ adw,
                             const float* __restrict__ W1, const float* __restrict__ b1,
                             int n) {
    const int NB = 16;
    int tid = threadIdx.x;
    int grp = tid >> 7;
    int t = tid & 127;
    int base = blockIdx.x * NB;
    __shared__ float4 sh[NB * 128];
    __shared__ float  sacc[NB * 128];
    __shared__ float  s_as[4][NB], s_ad[4][NB];

    const float4* W1_4 = (const float4*)W1;
    const float4* b1_4 = (const float4*)b1;

    for (int idx = tid; idx < NB * 128; idx += 256) {
        int m = idx >> 7, kq = idx & 127;
        int node = base + m;
        float4 v = make_float4(0.f, 0.f, 0.f, 0.f);
        if (node < n) {
            int h = kq >> 5;
            float A0 = g_a0[node * 4 + h];
            float A1 = g_a1[node * 4 + h];
            float4 w0 = W1_4[kq];
            float4 w1 = W1_4[128 + kq];
            float4 bb = b1_4[kq];
            v.x = fmaxf(fmaf(A0, w0.x, fmaf(A1, w1.x, bb.x)), 0.f);
            v.y = fmaxf(fmaf(A0, w0.y, fmaf(A1, w1.y, bb.y)), 0.f);
            v.z = fmaxf(fmaf(A0, w0.z, fmaf(A1, w1.z, bb.z)), 0.f);
            v.w = fmaxf(fmaf(A0, w0.w, fmaf(A1, w1.w, bb.w)), 0.f);
        }
        sh[idx] = v;
    }
    __syncthreads();

    const ulonglong2* shp = (const ulonglong2*)sh;   // f32x2-packed view
    unsigned long long acc2[NB];
#pragma unroll
    for (int m = 0; m < NB; m++) acc2[m] = pack_f2(0.f, 0.f);
    int kq0 = grp * 64;
    for (int kk = 0; kk < 64; kk++) {
        int kq = kq0 + kk;
        int k = kq * 4;
        unsigned long long wp01 = pack_f2(W2[(k + 0) * C + t], W2[(k + 1) * C + t]);
        unsigned long long wp23 = pack_f2(W2[(k + 2) * C + t], W2[(k + 3) * C + t]);
#pragma unroll
        for (int m = 0; m < NB; m++) {
            ulonglong2 sv = shp[m * 128 + kq];
            fma_f32x2(acc2[m], sv.x, wp01);
            fma_f32x2(acc2[m], sv.y, wp23);
        }
    }
    if (grp == 1) {
#pragma unroll
        for (int m = 0; m < NB; m++) {
            float2 pr = unpack_f2(acc2[m]);
            sacc[m * 128 + t] = pr.x + pr.y;
        }
    }
    __syncthreads();
    if (grp == 0) {
        float a_s = asw[t], a_d = adw[t];
        int w = t >> 5, lane = t & 31;
#pragma unroll
        for (int m = 0; m < NB; m++) {
            float2 pr = unpack_f2(acc2[m]);
            float hv = pr.x + pr.y + sacc[m * 128 + t];
            sacc[m * 128 + t] = hv;
            float vs = hv * a_s, vd = hv * a_d;
#pragma unroll
            for (int o = 16; o > 0; o >>= 1) {
                vs += __shfl_down_sync(0xFFFFFFFFu, vs, o);
                vd += __shfl_down_sync(0xFFFFFFFFu, vd, o);
            }
            if (lane == 0) { s_as[w][m] = vs; s_ad[w][m] = vd; }
        }
    }
    __syncthreads();
    if (tid < 32) {
        float v = -1e30f;
        if (tid < NB) {
            int node = base + tid;
            if (node < n) {
                float as2v = s_as[0][tid] + s_as[1][tid] + s_as[2][tid] + s_as[3][tid];
                g_as2[node] = as2v;
                g_ad2[node] = s_ad[0][tid] + s_ad[1][tid] + s_ad[2][tid] + s_ad[3][tid];
                v = as2v;
            }
        }
#pragma unroll
        for (int o = 16; o > 0; o >>= 1)
            v = fmaxf(v, __shfl_xor_sync(0xFFFFFFFFu, v, o));
        if (tid == 0) atomicMax(&g_as2max1, f2ord(v));
    }
    for (int idx = tid; idx < NB * 64; idx += 256) {
        int m = idx >> 6, p = idx & 63;
        int node = base + m;
        if (node < n) {
            __half2 hp = __floats2half2_rn(sacc[m * 128 + 2 * p], sacc[m * 128 + 2 * p + 1]);
            g_h2h[node * 64 + p] = hp;
        }
    }
}

// ---------------- layer 2: warp-per-node SINGLE-PASS softmax + fp16 aggregation ----------------
__global__ void __launch_bounds__(256) gat2_kernel(const float* __restrict__ b2,
                            const float* __restrict__ Wp, const float* __restrict__ bp,
                            float* __restrict__ out, int n) {
    __shared__ float s_p[8][ELLW];
    __shared__ int   s_src[8][ELLW];
    int tid = threadIdx.x;
    int w = tid >> 5, lane = tid & 31;
    int node = blockIdx.x * 8 + w;
    if (node >= n) return;

    int deg = min(g_cur[node], ELLW);
    const int* row = g_ell + node * ELLW;
    float ad = g_ad2[node];
    float bound = lrelu(ord2f(g_as2max1) + ad);

    // single pass: gather as2, exp against global bound
    float psum = 0.f;
    for (int j = lane; j < deg; j += 32) {
        int src = row[j];
        s_src[w][j] = src;
        float p = __expf(lrelu(g_as2[src] + ad) - bound);
        s_p[w][j] = p;
        psum += p;
    }
#pragma unroll
    for (int o = 16; o > 0; o >>= 1)
        psum += __shfl_xor_sync(0xFFFFFFFFu, psum, o);
    __syncwarp();

    // aggregation: thread handles channels 4*lane..4*lane+3, unrolled x2
    float4 acc = make_float4(0.f, 0.f, 0.f, 0.f);
    int j = 0;
    for (; j + 1 < deg; j += 2) {
        int src0 = s_src[w][j], src1 = s_src[w][j + 1];
        float p0 = s_p[w][j],   p1 = s_p[w][j + 1];
        uint2 r0 = *reinterpret_cast<const uint2*>(&g_h2h[src0 * 64 + 2 * lane]);
        uint2 r1 = *reinterpret_cast<const uint2*>(&g_h2h[src1 * 64 + 2 * lane]);
        float2 a0 = __half22float2(*reinterpret_cast<__half2*>(&r0.x));
        float2 b0 = __half22float2(*reinterpret_cast<__half2*>(&r0.y));
        float2 a1 = __half22float2(*reinterpret_cast<__half2*>(&r1.x));
        float2 b1v = __half22float2(*reinterpret_cast<__half2*>(&r1.y));
        acc.x += p0 * a0.x + p1 * a1.x;
        acc.y += p0 * a0.y + p1 * a1.y;
        acc.z += p0 * b0.x + p1 * b1v.x;
        acc.w += p0 * b0.y + p1 * b1v.y;
    }
    if (j < deg) {
        int src = s_src[w][j];
        float pj = s_p[w][j];
        uint2 raw = *reinterpret_cast<const uint2*>(&g_h2h[src * 64 + 2 * lane]);
        float2 fa = __half22float2(*reinterpret_cast<__half2*>(&raw.x));
        float2 fb = __half22float2(*reinterpret_cast<__half2*>(&raw.y));
        acc.x += pj * fa.x; acc.y += pj * fa.y;
        acc.z += pj * fb.x; acc.w += pj * fb.y;
    }

    float inv = 1.f / (psum + 1e-16f);
    float4 bq = ((const float4*)b2)[lane];
    float4 wq = ((const float4*)Wp)[lane];
    float o0 = fmaxf(acc.x * inv + bq.x, 0.f);
    float o1 = fmaxf(acc.y * inv + bq.y, 0.f);
    float o2 = fmaxf(acc.z * inv + bq.z, 0.f);
    float o3 = fmaxf(acc.w * inv + bq.w, 0.f);
    float v = o0 * wq.x + o1 * wq.y + o2 * wq.z + o3 * wq.w;
#pragma unroll
    for (int o = 16; o > 0; o >>= 1)
        v += __shfl_down_sync(0xFFFFFFFFu, v, o);
    if (lane == 0) out[node] = v + bp[0];
}

// ---------------- launch ----------------
extern "C" void kernel_launch(void* const* d_in, const int* in_sizes, int n_in,
                              void* d_out, int out_size) {
    const float* x    = (const float*)d_in[0];
    const int*   ei32 = (const int*)d_in[1];
    const float* W1   = (const float*)d_in[2];
    const float* as1w = (const float*)d_in[3];
    const float* ad1w = (const float*)d_in[4];
    const float* b1   = (const float*)d_in[5];
    const float* W2   = (const float*)d_in[6];
    const float* as2w = (const float*)d_in[7];
    const float* ad2w = (const float*)d_in[8];
    const float* b2   = (const float*)d_in[9];
    const float* Wp   = (const float*)d_in[10];
    const float* bp   = (const float*)d_in[11];
    float* out = (float*)d_out;

    int n = in_sizes[0] / 2;   // x is [N,2]
    int e = in_sizes[1] / 2;   // edge_index is [2,E]

    prep_kernel<<<1, 128>>>(ei32, W1, as1w, ad1w);
    ell_init_kernel<<<(n + 255) / 256, 256>>>(x, n);
    scatter_kernel<<<(e + 255) / 256, 256>>>(ei32, e);

    gat1_kernel<<<(n + 7) / 8, 256>>>(x, n);
    gemm2_kernel<<<(n + 15) / 16, 256>>>(W2, as2w, ad2w, W1, b1, n);
    gat2_kernel<<<(n + 7) / 8, 256>>>(b2, Wp, bp, out, n);
}